// round 2
// baseline (speedup 1.0000x reference)
#include <cuda_runtime.h>
#include <math_constants.h>

#define BATCH   2
#define S_LEN   2048
#define D_MODEL 1024
#define NH      16
#define HDIM    64   // DK == DV == 64

// ---------------- scratch (device globals: no allocation allowed) ----------
__device__ float g_q[BATCH * NH * S_LEN * HDIM];     // [B,H,S,64]
__device__ float g_k[BATCH * NH * S_LEN * HDIM];
__device__ float g_v[BATCH * NH * S_LEN * HDIM];
__device__ float g_att[BATCH * S_LEN * D_MODEL];     // [B,S,H*64]

// ---------------- SGEMM: C[4096][1024] = A[4096][1024] @ W[1024][1024] + b --
#define BM 128
#define BN 128
#define BK 16

// MODE 0: plain row-major output. MODE 1: scatter to [B,H,S,64] (q/k/v layout)
template <int MODE>
__device__ __forceinline__ void gemm_tile(const float* __restrict__ A,
                                          const float* __restrict__ W,
                                          const float* __restrict__ bias,
                                          float* __restrict__ C)
{
    __shared__ float As[BK][BM];   // A stored transposed: As[k][m]
    __shared__ float Bs[BK][BN];

    const int tid = threadIdx.x;
    const int bm  = blockIdx.y * BM;
    const int bn  = blockIdx.x * BN;
    const int tx  = tid & 15;
    const int ty  = tid >> 4;

    float acc[8][8];
#pragma unroll
    for (int i = 0; i < 8; i++)
#pragma unroll
        for (int j = 0; j < 8; j++) acc[i][j] = 0.f;

    const int arow = tid >> 2;         // 0..63 (+64 on second pass)
    const int acol = (tid & 3) << 2;   // 0,4,8,12
    const int brow = tid >> 5;         // 0..7  (+8 on second pass)
    const int bcol = (tid & 31) << 2;  // 0..124

    for (int k0 = 0; k0 < D_MODEL; k0 += BK) {
#pragma unroll
        for (int i = 0; i < 2; i++) {
            const int r = arow + i * 64;
            float4 a = *(const float4*)(A + (size_t)(bm + r) * D_MODEL + k0 + acol);
            As[acol + 0][r] = a.x;
            As[acol + 1][r] = a.y;
            As[acol + 2][r] = a.z;
            As[acol + 3][r] = a.w;
        }
#pragma unroll
        for (int i = 0; i < 2; i++) {
            const int r = brow + i * 8;
            *(float4*)&Bs[r][bcol] =
                *(const float4*)(W + (size_t)(k0 + r) * D_MODEL + bn + bcol);
        }
        __syncthreads();

#pragma unroll
        for (int kk = 0; kk < BK; kk++) {
            float af[8], bf[8];
            *(float4*)&af[0] = *(float4*)&As[kk][ty * 4];
            *(float4*)&af[4] = *(float4*)&As[kk][64 + ty * 4];
            *(float4*)&bf[0] = *(float4*)&Bs[kk][tx * 4];
            *(float4*)&bf[4] = *(float4*)&Bs[kk][64 + tx * 4];
#pragma unroll
            for (int i = 0; i < 8; i++)
#pragma unroll
                for (int j = 0; j < 8; j++)
                    acc[i][j] = fmaf(af[i], bf[j], acc[i][j]);
        }
        __syncthreads();
    }

#pragma unroll
    for (int i = 0; i < 8; i++) {
        const int m = bm + ((i < 4) ? (ty * 4 + i) : (64 + ty * 4 + i - 4));
#pragma unroll
        for (int j = 0; j < 8; j++) {
            const int n = bn + ((j < 4) ? (tx * 4 + j) : (64 + tx * 4 + j - 4));
            const float val = acc[i][j] + bias[n];
            if (MODE == 0) {
                C[(size_t)m * D_MODEL + n] = val;
            } else {
                const int b = m >> 11, s = m & (S_LEN - 1);
                const int h = n >> 6, d = n & 63;
                C[(((size_t)b * NH + h) * S_LEN + s) * HDIM + d] = val;
            }
        }
    }
}

__global__ __launch_bounds__(256) void gemm_qkv_kernel(
    const float* __restrict__ x,
    const float* __restrict__ Wq, const float* __restrict__ bq,
    const float* __restrict__ Wk, const float* __restrict__ bk,
    const float* __restrict__ Wv, const float* __restrict__ bv)
{
    const float* W;
    const float* bias;
    float* out;
    if (blockIdx.z == 0)      { W = Wq; bias = bq; out = g_q; }
    else if (blockIdx.z == 1) { W = Wk; bias = bk; out = g_k; }
    else                      { W = Wv; bias = bv; out = g_v; }
    gemm_tile<1>(x, W, bias, out);
}

__global__ __launch_bounds__(256) void gemm_out_kernel(
    const float* __restrict__ Wo, const float* __restrict__ bo,
    float* __restrict__ out)
{
    gemm_tile<0>(g_att, Wo, bo, out);
}

// ---------------- flash attention (causal + key padding mask) --------------
// One block = 128 query rows of one (b,h). One thread = one query row.
// dynamic smem: Q^T [64][128] + K^T [64][32] + V [32][64] + mask[32] = 49280 B
#define FBR 128
#define FBC 32
#define FLASH_SMEM_BYTES ((64 * 128 + 64 * FBC + FBC * 64 + FBC) * 4)

__global__ __launch_bounds__(128) void flash_kernel(const unsigned char* __restrict__ mask)
{
    extern __shared__ float sm[];
    float* qst = sm;                         // [64][128]  qst[d][row]
    float* Kst = sm + 64 * 128;              // [64][32]   Kst[d][j]
    float* Vs  = sm + 64 * 128 + 64 * FBC;   // [32][64]   Vs[j][d]
    int*   maskS = (int*)(sm + 64 * 128 + 64 * FBC + FBC * 64);  // [32]

    const int tid = threadIdx.x;
    const int qt  = (gridDim.x - 1) - blockIdx.x;   // big tiles first (load balance)
    const int h   = blockIdx.y;
    const int b   = blockIdx.z;
    const size_t bh = (size_t)b * NH + h;
    const float* qb = g_q + bh * S_LEN * HDIM;
    const float* kb = g_k + bh * S_LEN * HDIM;
    const float* vb = g_v + bh * S_LEN * HDIM;

    // stage Q tile transposed (once per block)
#pragma unroll
    for (int p = 0; p < 16; p++) {
        const int idx = p * 128 + tid;
        const int row = idx >> 4;
        const int d4  = (idx & 15) << 2;
        float4 qv = *(const float4*)(qb + (size_t)(qt * FBR + row) * HDIM + d4);
        qst[(d4 + 0) * 128 + row] = qv.x;
        qst[(d4 + 1) * 128 + row] = qv.y;
        qst[(d4 + 2) * 128 + row] = qv.z;
        qst[(d4 + 3) * 128 + row] = qv.w;
    }

    float acc[HDIM];
#pragma unroll
    for (int d = 0; d < HDIM; d++) acc[d] = 0.f;
    float mrow = -CUDART_INF_F;
    float lrow = 0.f;

    const int row_g = qt * FBR + tid;
    const int nkt   = (qt + 1) * (FBR / FBC);
    const int diag0 = qt * (FBR / FBC);

    for (int kt = 0; kt < nkt; kt++) {
        __syncthreads();   // previous-iteration smem reads done
#pragma unroll
        for (int p = 0; p < 4; p++) {
            const int idx = p * 128 + tid;
            const int j   = idx >> 4;
            const int d4  = (idx & 15) << 2;
            const size_t goff = (size_t)(kt * FBC + j) * HDIM + d4;
            float4 kv = *(const float4*)(kb + goff);
            Kst[(d4 + 0) * FBC + j] = kv.x;
            Kst[(d4 + 1) * FBC + j] = kv.y;
            Kst[(d4 + 2) * FBC + j] = kv.z;
            Kst[(d4 + 3) * FBC + j] = kv.w;
            *(float4*)(Vs + j * HDIM + d4) = *(const float4*)(vb + goff);
        }
        if (tid < FBC) maskS[tid] = mask[(size_t)b * S_LEN + kt * FBC + tid];
        __syncthreads();

        // scores: s[j] = q(row) . k(j)    (K reads are warp-broadcast)
        float s[FBC];
#pragma unroll
        for (int j = 0; j < FBC; j++) s[j] = 0.f;
#pragma unroll 4
        for (int d = 0; d < HDIM; d++) {
            const float qd = qst[d * 128 + tid];
#pragma unroll
            for (int j4 = 0; j4 < 8; j4++) {
                float4 kk = *(float4*)(Kst + d * FBC + j4 * 4);
                s[j4 * 4 + 0] = fmaf(qd, kk.x, s[j4 * 4 + 0]);
                s[j4 * 4 + 1] = fmaf(qd, kk.y, s[j4 * 4 + 1]);
                s[j4 * 4 + 2] = fmaf(qd, kk.z, s[j4 * 4 + 2]);
                s[j4 * 4 + 3] = fmaf(qd, kk.w, s[j4 * 4 + 3]);
            }
        }

        float mt = mrow;
        const bool need_causal = (kt >= diag0);
#pragma unroll
        for (int j = 0; j < FBC; j++) {
            float sv = s[j] * 0.125f;   // 1/sqrt(64)
            if ((need_causal && (kt * FBC + j > row_g)) || maskS[j])
                sv = -CUDART_INF_F;
            s[j] = sv;
            mt = fmaxf(mt, sv);
        }

        if (mt > -CUDART_INF_F) {
            const float scale = (mrow > -CUDART_INF_F) ? __expf(mrow - mt) : 0.f;
            mrow = mt;
            float psum = 0.f;
#pragma unroll
            for (int j = 0; j < FBC; j++) {
                const float p = __expf(s[j] - mt);
                s[j] = p;
                psum += p;
            }
            lrow = lrow * scale + psum;
#pragma unroll
            for (int d = 0; d < HDIM; d++) acc[d] *= scale;
            // PV: V reads are warp-broadcast
#pragma unroll
            for (int j = 0; j < FBC; j++) {
                const float pj = s[j];
#pragma unroll
                for (int d4 = 0; d4 < 16; d4++) {
                    float4 vv = *(float4*)(Vs + j * HDIM + d4 * 4);
                    acc[d4 * 4 + 0] = fmaf(pj, vv.x, acc[d4 * 4 + 0]);
                    acc[d4 * 4 + 1] = fmaf(pj, vv.y, acc[d4 * 4 + 1]);
                    acc[d4 * 4 + 2] = fmaf(pj, vv.z, acc[d4 * 4 + 2]);
                    acc[d4 * 4 + 3] = fmaf(pj, vv.w, acc[d4 * 4 + 3]);
                }
            }
        }
    }

    const float inv = 1.f / lrow;
    float* op = g_att + ((size_t)b * S_LEN + row_g) * D_MODEL + h * HDIM;
#pragma unroll
    for (int d4 = 0; d4 < 16; d4++) {
        float4 w;
        w.x = acc[d4 * 4 + 0] * inv;
        w.y = acc[d4 * 4 + 1] * inv;
        w.z = acc[d4 * 4 + 2] * inv;
        w.w = acc[d4 * 4 + 3] * inv;
        *(float4*)(op + d4 * 4) = w;
    }
}

// ---------------- launch ----------------------------------------------------
extern "C" void kernel_launch(void* const* d_in, const int* in_sizes, int n_in,
                              void* d_out, int out_size)
{
    const float* x  = (const float*)d_in[0];
    const unsigned char* mask = (const unsigned char*)d_in[1];
    const float* Wq = (const float*)d_in[2];
    const float* bq = (const float*)d_in[3];
    const float* Wk = (const float*)d_in[4];
    const float* bk = (const float*)d_in[5];
    const float* Wv = (const float*)d_in[6];
    const float* bv = (const float*)d_in[7];
    const float* Wo = (const float*)d_in[8];
    const float* bo = (const float*)d_in[9];
    float* out = (float*)d_out;

    // opt-in for >48KB-adjacent dynamic smem (not a stream op: capture-safe)
    cudaFuncSetAttribute(flash_kernel,
                         cudaFuncAttributeMaxDynamicSharedMemorySize,
                         FLASH_SMEM_BYTES);

    // 1) fused QKV projections -> g_q/g_k/g_v in [B,H,S,64]
    dim3 gq(D_MODEL / BN, (BATCH * S_LEN) / BM, 3);
    gemm_qkv_kernel<<<gq, 256>>>(x, Wq, bq, Wk, bk, Wv, bv);

    // 2) causal flash attention -> g_att in [B,S,1024]
    dim3 gf(S_LEN / FBR, NH, BATCH);
    flash_kernel<<<gf, 128, FLASH_SMEM_BYTES>>>(mask);

    // 3) output projection -> d_out
    dim3 go(D_MODEL / BN, (BATCH * S_LEN) / BM, 1);
    gemm_out_kernel<<<go, 256>>>(Wo, bo, out);
}